// round 13
// baseline (speedup 1.0000x reference)
#include <cuda_runtime.h>
#include <cuda_bf16.h>
#include <math.h>
#include <stdint.h>

// ---------------- problem constants ----------------
#define BATCH 2
#define HEADS 16
#define SEQ   4096
#define DIM   64
#define HID   1024
#define NHASH 2
#define NBUCK 128
#define CHUNK 64
#define BH    (BATCH*HEADS)          // 32
#define SH    (NHASH*SEQ)            // 8192
#define NCH   (SH/CHUNK)             // 128

// ---------------- scratch (device globals; no allocation allowed) ----------
__device__ float g_qk[BH*SEQ*DIM];
__device__ float g_v [BH*SEQ*DIM];
__device__ unsigned char  g_buckets[BH*SH];
__device__ unsigned short g_sorted[BH*SH];
__device__ unsigned short g_undo[BH*SH];
__device__ float g_outs[BH*SH*DIM];
__device__ float g_logits[BH*SH];

// ---------------- fused projection GEMM -------------------------------------
// z=0: v = A @ Wv^T via 3xTF32 mma.sync (tensor pipe; v is linear => safe)
// z=1: qk = A @ Wqk^T via exact fp32 FFMA (fma pipe; bucket-critical)
// Co-resident CTAs of both kinds overlap the two pipes on each SM.
__device__ __forceinline__ uint32_t f2tf32(float x){
    uint32_t r;
    asm("cvt.rna.tf32.f32 %0, %1;" : "=r"(r) : "f"(x));
    return r;
}
__device__ __forceinline__ void mma_tf32(float* d,
    uint32_t a0, uint32_t a1, uint32_t a2, uint32_t a3,
    uint32_t b0, uint32_t b1)
{
    asm volatile(
        "mma.sync.aligned.m16n8k8.row.col.f32.tf32.tf32.f32 "
        "{%0,%1,%2,%3}, {%4,%5,%6,%7}, {%8,%9}, {%0,%1,%2,%3};"
        : "+f"(d[0]), "+f"(d[1]), "+f"(d[2]), "+f"(d[3])
        : "r"(a0), "r"(a1), "r"(a2), "r"(a3), "r"(b0), "r"(b1));
}

#define MPITCH 140
#define PROJ_SMEM_BYTES (4*16*MPITCH*4)   // 35840 (tf32 path is the larger)

__global__ __launch_bounds__(256) void proj_kernel(
    const float* __restrict__ A, const float* __restrict__ Wqk,
    const float* __restrict__ Wv)
{
    __shared__ __align__(16) unsigned char smbuf[PROJ_SMEM_BYTES];

    int bn = blockIdx.x;          // 0..7
    int bm = blockIdx.y;          // 0..63
    int tid = threadIdx.x;

    if (blockIdx.z == 0) {
        // ---------------- tf32 tensor path: v --------------------------------
        uint32_t (*AsH)[MPITCH] = (uint32_t(*)[MPITCH])(smbuf);
        uint32_t (*AsL)[MPITCH] = (uint32_t(*)[MPITCH])(smbuf + 16*MPITCH*4);
        uint32_t (*BsH)[MPITCH] = (uint32_t(*)[MPITCH])(smbuf + 2*16*MPITCH*4);
        uint32_t (*BsL)[MPITCH] = (uint32_t(*)[MPITCH])(smbuf + 3*16*MPITCH*4);

        const float* W = Wv;
        float* Cdst    = g_v;

        int wid  = tid >> 5;
        int lane = tid & 31;
        int wm = wid & 3;
        int wn = wid >> 2;
        int g  = lane >> 2;
        int c  = lane & 3;

        int lrow = tid >> 1;
        int kq   = (tid & 1) * 4;
        const float* Aptr = A + (long)(bm*128 + lrow)*HID + kq;
        const float* Wptr = W + (long)(bn*128 + lrow)*HID + kq;

        float acc[2][8][4];
#pragma unroll
        for (int mt = 0; mt < 2; mt++)
#pragma unroll
            for (int nt = 0; nt < 8; nt++)
#pragma unroll
                for (int r = 0; r < 4; r++) acc[mt][nt][r] = 0.f;

        float4 pa0 = *(const float4*)(Aptr);
        float4 pa1 = *(const float4*)(Aptr + 8);
        float4 pw0 = *(const float4*)(Wptr);
        float4 pw1 = *(const float4*)(Wptr + 8);

#pragma unroll 1
        for (int st = 0; st < 64; st++) {
            __syncthreads();
            {
                float xa[8] = {pa0.x,pa0.y,pa0.z,pa0.w, pa1.x,pa1.y,pa1.z,pa1.w};
                float xw[8] = {pw0.x,pw0.y,pw0.z,pw0.w, pw1.x,pw1.y,pw1.z,pw1.w};
#pragma unroll
                for (int j = 0; j < 8; j++) {
                    int kk = kq + (j & 3) + (j >> 2)*8;
                    uint32_t h = f2tf32(xa[j]);
                    uint32_t l = f2tf32(xa[j] - __uint_as_float(h));
                    AsH[kk][lrow] = h; AsL[kk][lrow] = l;
                    h = f2tf32(xw[j]);
                    l = f2tf32(xw[j] - __uint_as_float(h));
                    BsH[kk][lrow] = h; BsL[kk][lrow] = l;
                }
            }
            __syncthreads();

            if (st + 1 < 64) {
                int k0n = (st+1)*16;
                pa0 = *(const float4*)(Aptr + k0n);
                pa1 = *(const float4*)(Aptr + k0n + 8);
                pw0 = *(const float4*)(Wptr + k0n);
                pw1 = *(const float4*)(Wptr + k0n + 8);
            }

#pragma unroll
            for (int ks = 0; ks < 2; ks++) {
                int k = ks*8;
                uint32_t ah[2][4], al[2][4];
#pragma unroll
                for (int mt = 0; mt < 2; mt++) {
                    int m = wm*32 + mt*16 + g;
                    ah[mt][0] = AsH[k + c    ][m];
                    ah[mt][1] = AsH[k + c    ][m + 8];
                    ah[mt][2] = AsH[k + c + 4][m];
                    ah[mt][3] = AsH[k + c + 4][m + 8];
                    al[mt][0] = AsL[k + c    ][m];
                    al[mt][1] = AsL[k + c    ][m + 8];
                    al[mt][2] = AsL[k + c + 4][m];
                    al[mt][3] = AsL[k + c + 4][m + 8];
                }
                uint32_t bh[8][2], bl[8][2];
#pragma unroll
                for (int nt = 0; nt < 8; nt++) {
                    int n = wn*64 + nt*8 + g;
                    bh[nt][0] = BsH[k + c    ][n];
                    bh[nt][1] = BsH[k + c + 4][n];
                    bl[nt][0] = BsL[k + c    ][n];
                    bl[nt][1] = BsL[k + c + 4][n];
                }
#pragma unroll
                for (int mt = 0; mt < 2; mt++)
#pragma unroll
                    for (int nt = 0; nt < 8; nt++) {
                        mma_tf32(acc[mt][nt], ah[mt][0],ah[mt][1],ah[mt][2],ah[mt][3],
                                 bh[nt][0], bh[nt][1]);
                        mma_tf32(acc[mt][nt], ah[mt][0],ah[mt][1],ah[mt][2],ah[mt][3],
                                 bl[nt][0], bl[nt][1]);
                        mma_tf32(acc[mt][nt], al[mt][0],al[mt][1],al[mt][2],al[mt][3],
                                 bh[nt][0], bh[nt][1]);
                    }
            }
        }

#pragma unroll
        for (int mt = 0; mt < 2; mt++) {
#pragma unroll
            for (int nt = 0; nt < 8; nt++) {
                int m = bm*128 + wm*32 + mt*16 + g;
                int n = bn*128 + wn*64 + nt*8 + c*2;
                int b = m >> 12, s = m & 4095;
                int h = n >> 6,  d = n & 63;
                float2 o0 = make_float2(acc[mt][nt][0], acc[mt][nt][1]);
                float2 o1 = make_float2(acc[mt][nt][2], acc[mt][nt][3]);
                long base = ((long)(b*HEADS + h)*SEQ);
                *(float2*)&Cdst[(base + s    )*DIM + d] = o0;
                *(float2*)&Cdst[(base + s + 8)*DIM + d] = o1;
            }
        }
    } else {
        // ---------------- fp32 fma path: qk (exact, bucket-critical) ---------
        float (*As)[8][132] = (float(*)[8][132])(smbuf);
        float (*Bs)[8][132] = (float(*)[8][132])(smbuf + 2*8*132*4);

        const float* W = Wqk;
        float* Cdst    = g_qk;
        const int K = HID;

        int tx = tid & 15;
        int ty = tid >> 4;

        int lrow = tid >> 1;
        int kq   = (tid & 1) * 4;
        const float* Aptr = A + ((long)(bm*128 + lrow))*K + kq;
        const float* Wptr = W + ((long)(bn*128 + lrow))*K + kq;

        float acc[8][8];
#pragma unroll
        for (int i = 0; i < 8; i++)
#pragma unroll
            for (int j = 0; j < 8; j++) acc[i][j] = 0.f;

        {
            float4 pa = *(const float4*)(Aptr);
            float4 pb = *(const float4*)(Wptr);
            As[0][kq+0][lrow] = pa.x; As[0][kq+1][lrow] = pa.y;
            As[0][kq+2][lrow] = pa.z; As[0][kq+3][lrow] = pa.w;
            Bs[0][kq+0][lrow] = pb.x; Bs[0][kq+1][lrow] = pb.y;
            Bs[0][kq+2][lrow] = pb.z; Bs[0][kq+3][lrow] = pb.w;
        }
        __syncthreads();

        int stage = 0;
#pragma unroll 1
        for (int k0 = 0; k0 < K; k0 += 8) {
            bool has = (k0 + 8) < K;
            float4 pa, pb;
            if (has) {
                pa = *(const float4*)(Aptr + k0 + 8);
                pb = *(const float4*)(Wptr + k0 + 8);
            }
#pragma unroll
            for (int k = 0; k < 8; k++) {
                float a[8], b[8];
                *(float4*)(a)   = *(const float4*)&As[stage][k][ty*8];
                *(float4*)(a+4) = *(const float4*)&As[stage][k][ty*8+4];
                *(float4*)(b)   = *(const float4*)&Bs[stage][k][tx*4];
                *(float4*)(b+4) = *(const float4*)&Bs[stage][k][64 + tx*4];
#pragma unroll
                for (int i = 0; i < 8; i++)
#pragma unroll
                    for (int j = 0; j < 8; j++) acc[i][j] += a[i]*b[j];
            }
            if (has) {
                int ns = stage ^ 1;
                As[ns][kq+0][lrow] = pa.x; As[ns][kq+1][lrow] = pa.y;
                As[ns][kq+2][lrow] = pa.z; As[ns][kq+3][lrow] = pa.w;
                Bs[ns][kq+0][lrow] = pb.x; Bs[ns][kq+1][lrow] = pb.y;
                Bs[ns][kq+2][lrow] = pb.z; Bs[ns][kq+3][lrow] = pb.w;
                __syncthreads();
                stage = ns;
            }
        }

#pragma unroll
        for (int i = 0; i < 8; i++) {
            int m = bm*128 + ty*8 + i;
            int b = m >> 12, s = m & 4095;
            int n0 = bn*128 + tx*4;
            int n1 = n0 + 64;
            float4 o0 = make_float4(acc[i][0], acc[i][1], acc[i][2], acc[i][3]);
            float4 o1 = make_float4(acc[i][4], acc[i][5], acc[i][6], acc[i][7]);
            *(float4*)&Cdst[((b*HEADS + (n0>>6))*SEQ + s)*DIM + (n0&63)] = o0;
            *(float4*)&Cdst[((b*HEADS + (n1>>6))*SEQ + s)*DIM + (n1&63)] = o1;
        }
    }
}

// ---------------- hashing: argmax over [rot, -rot] per hash round ----------
#define HTOK 32
__global__ __launch_bounds__(128) void hash_kernel(const float* __restrict__ rot)
{
    __shared__ float rs[DIM*128];       // 32 KB
    __shared__ float q[HTOK][DIM];      // 8 KB
    __shared__ float sv[HTOK][4];
    __shared__ int   si[HTOK][4];

    int tid = threadIdx.x;
    int g0  = blockIdx.x * HTOK;

    for (int i = tid; i < DIM*128; i += 128) rs[i] = rot[i];
    for (int i = tid; i < HTOK*DIM; i += 128) {
        int t = i >> 6, d = i & 63;
        q[t][d] = g_qk[(g0 + t)*DIM + d];
    }
    __syncthreads();

    int warp = tid >> 5, lane = tid & 31;
    int r = tid & 63;

#pragma unroll 4
    for (int t = 0; t < HTOK; t++) {
        float val = 0.f;
#pragma unroll
        for (int d = 0; d < DIM; d++) val += q[t][d] * rs[d*128 + tid];

        float bv; int bi;
        if (val >= -val) { bv = val;  bi = r; }
        else             { bv = -val; bi = r + 64; }
#pragma unroll
        for (int off = 16; off; off >>= 1) {
            float ov = __shfl_down_sync(0xffffffffu, bv, off);
            int   oi = __shfl_down_sync(0xffffffffu, bi, off);
            if (ov > bv || (ov == bv && oi < bi)) { bv = ov; bi = oi; }
        }
        if (lane == 0) { sv[t][warp] = bv; si[t][warp] = bi; }
    }
    __syncthreads();

    if (tid < HTOK*2) {
        int t = tid >> 1, n = tid & 1;
        float v0 = sv[t][n*2];   int i0 = si[t][n*2];
        float v1 = sv[t][n*2+1]; int i1 = si[t][n*2+1];
        if (v1 > v0 || (v1 == v0 && i1 < i0)) { v0 = v1; i0 = i1; }
        int bucket = i0 + n*NBUCK;
        int gidx = g0 + t;
        int bh = gidx >> 12;
        int s  = gidx & 4095;
        g_buckets[bh*SH + n*SEQ + s] = (unsigned char)bucket;
    }
}

// ---------------- stable counting sort per (b,h) ---------------------------
__global__ __launch_bounds__(256) void sort_kernel()
{
    int bh = blockIdx.x;
    __shared__ unsigned char bk[SH];
    __shared__ unsigned int  gh[32][256];
    __shared__ unsigned int  hist[256];
    int tid = threadIdx.x;

    const unsigned char* src = &g_buckets[bh*SH];
    for (int i = tid; i < SH; i += 256) bk[i] = src[i];
    for (int g = 0; g < 32; g++) gh[g][tid] = 0;
    __syncthreads();

    {
        int g = tid >> 3, lane = tid & 7;
        for (int k = 0; k < 32; k++) {
            int idx = g*256 + lane + k*8;
            int pos = idx >> 1, n = idx & 1;
            atomicAdd(&gh[g][bk[n*SEQ + pos]], 1u);
        }
    }
    __syncthreads();

    {
        unsigned int running = 0;
        for (int g = 0; g < 32; g++) {
            unsigned int t = gh[g][tid];
            gh[g][tid] = running;
            running += t;
        }
        hist[tid] = running;
    }
    __syncthreads();
    if (tid == 0) {
        unsigned int acc = 0;
        for (int b = 0; b < 256; b++) { unsigned int t = hist[b]; hist[b] = acc; acc += t; }
    }
    __syncthreads();
    for (int g = 0; g < 32; g++) gh[g][tid] += hist[tid];
    __syncthreads();

    if (tid < 32) {
        unsigned short* outS = &g_sorted[bh*SH];
        unsigned short* outU = &g_undo[bh*SH];
        for (int i = 0; i < 256; i++) {
            int idx = tid*256 + i;
            int pos = idx >> 1, n = idx & 1;
            int t = n*SEQ + pos;
            int b = bk[t];
            unsigned int dest = gh[tid][b]++;
            outS[dest] = (unsigned short)t;
            outU[t]    = (unsigned short)dest;
        }
    }
}

// ---------------- chunked attention ---------------------------------------
#define KT_PITCH 132
#define V_PITCH  68
#define P_PITCH  68
#define ATTN_SMEM ((64*KT_PITCH + 128*V_PITCH + 128*P_PITCH + 128 + 64 + 128)*4)

__global__ __launch_bounds__(256) void attn_kernel()
{
    extern __shared__ float sm[];
    float* kt     = sm;                         // [64 d][132 rows]
    float* vs     = kt + 64*KT_PITCH;           // [128 rows][68 d]
    float* pt     = vs + 128*V_PITCH;           // [128 kc][68 q]
    float* rnorm  = pt + 128*P_PITCH;           // 128
    float* rowlog = rnorm + 128;                // 64
    int*   tick   = (int*)(rowlog + 64);        // 128

    int chunk = blockIdx.x & (NCH-1);
    int bh    = blockIdx.x >> 7;
    int tid   = threadIdx.x;

    if (tid < 128) {
        int sp = (chunk*CHUNK + (SH - CHUNK) + tid) & (SH-1);
        int t  = g_sorted[bh*SH + sp];
        tick[tid] = t & (SEQ-1);
    }
    __syncthreads();

    for (int rr = 0; rr < 128; rr += 4) {
        int row = rr + (tid >> 6);
        int d   = tid & 63;
        int s   = tick[row];
        int base = (bh*SEQ + s)*DIM + d;
        kt[d*KT_PITCH + row] = g_qk[base];
        vs[row*V_PITCH + d]  = g_v[base];
    }
    __syncthreads();

    if (tid < 128) {
        float ss = 0.f;
#pragma unroll
        for (int d = 0; d < DIM; d++) { float x = kt[d*KT_PITCH + tid]; ss += x*x; }
        rnorm[tid] = rsqrtf(ss * (1.0f/DIM) + 1e-6f) * 0.125f;
    }
    __syncthreads();

    int tx = tid & 15;
    int ty = tid >> 4;

    {
        float acc[8][4];
#pragma unroll
        for (int i = 0; i < 8; i++)
#pragma unroll
            for (int j = 0; j < 4; j++) acc[i][j] = 0.f;

#pragma unroll 4
        for (int d = 0; d < DIM; d++) {
            float a[8], b[4];
            const float* kr = &kt[d*KT_PITCH];
            *(float4*)(a)    = *(const float4*)&kr[ty*8];
            *(float4*)(a+4)  = *(const float4*)&kr[ty*8+4];
            *(float4*)(b)    = *(const float4*)&kr[64 + tx*4];
#pragma unroll
            for (int i = 0; i < 8; i++)
#pragma unroll
                for (int j = 0; j < 4; j++) acc[i][j] += a[i]*b[j];
        }

        int tq[4];
#pragma unroll
        for (int j = 0; j < 4; j++) tq[j] = tick[64 + tx*4 + j];

#pragma unroll
        for (int i = 0; i < 8; i++) {
            int kc = ty*8 + i;
            float rn = rnorm[kc];
            int tk = tick[kc];
            float4 o;
            float v0 = acc[i][0]*rn, v1 = acc[i][1]*rn,
                  v2 = acc[i][2]*rn, v3 = acc[i][3]*rn;
            if (tq[0] <  tk) v0 = -1e9f; else if (tq[0] == tk) v0 = -1e5f;
            if (tq[1] <  tk) v1 = -1e9f; else if (tq[1] == tk) v1 = -1e5f;
            if (tq[2] <  tk) v2 = -1e9f; else if (tq[2] == tk) v2 = -1e5f;
            if (tq[3] <  tk) v3 = -1e9f; else if (tq[3] == tk) v3 = -1e5f;
            o.x = v0; o.y = v1; o.z = v2; o.w = v3;
            *(float4*)&pt[kc*P_PITCH + tx*4] = o;
        }
    }
    __syncthreads();

    {
        int row = tid >> 2, quar = tid & 3;
        float m = -3.4e38f;
        for (int c = 0; c < 32; c++)
            m = fmaxf(m, pt[(quar*32 + c)*P_PITCH + row]);
        m = fmaxf(m, __shfl_xor_sync(0xffffffffu, m, 1));
        m = fmaxf(m, __shfl_xor_sync(0xffffffffu, m, 2));
        float ssum = 0.f;
        for (int c = 0; c < 32; c++)
            ssum += __expf(pt[(quar*32 + c)*P_PITCH + row] - m);
        ssum += __shfl_xor_sync(0xffffffffu, ssum, 1);
        ssum += __shfl_xor_sync(0xffffffffu, ssum, 2);
        float lg = m + __logf(ssum);
        if (quar == 0) rowlog[row] = lg;
        for (int c = 0; c < 32; c++) {
            int idx = (quar*32 + c)*P_PITCH + row;
            pt[idx] = __expf(pt[idx] - lg);
        }
    }
    __syncthreads();

    {
        float acc2[4][4];
#pragma unroll
        for (int i = 0; i < 4; i++)
#pragma unroll
            for (int j = 0; j < 4; j++) acc2[i][j] = 0.f;

#pragma unroll 4
        for (int kc = 0; kc < 128; kc++) {
            float a2[4], b2[4];
            *(float4*)(a2) = *(const float4*)&pt[kc*P_PITCH + ty*4];
            *(float4*)(b2) = *(const float4*)&vs[kc*V_PITCH + tx*4];
#pragma unroll
            for (int i = 0; i < 4; i++)
#pragma unroll
                for (int j = 0; j < 4; j++) acc2[i][j] += a2[i]*b2[j];
        }

#pragma unroll
        for (int i = 0; i < 4; i++) {
            int q = ty*4 + i;
            float4 o; o.x = acc2[i][0]; o.y = acc2[i][1];
                      o.z = acc2[i][2]; o.w = acc2[i][3];
            *(float4*)&g_outs[((long)(bh*SH + chunk*CHUNK + q))*DIM + tx*4] = o;
        }
        if (tid < 64)
            g_logits[bh*SH + chunk*CHUNK + tid] = rowlog[tid];
    }
}

// ---------------- combine hash rounds + write output -----------------------
__global__ __launch_bounds__(256) void combine_kernel(float* __restrict__ out)
{
    int i = blockIdx.x*256 + threadIdx.x;
    int d  = i & 63;
    int r  = i >> 6;
    int s  = r & (SEQ-1);
    int bh = r >> 12;
    int base = bh*SH;

    int p0 = g_undo[base + s];
    int p1 = g_undo[base + SEQ + s];
    float l0 = g_logits[base + p0];
    float l1 = g_logits[base + p1];
    float m  = fmaxf(l0, l1);
    float w0 = __expf(l0 - m);
    float w1 = __expf(l1 - m);
    float inv = 1.0f / (w0 + w1);
    float o = (w0 * g_outs[(base + p0)*DIM + d] +
               w1 * g_outs[(base + p1)*DIM + d]) * inv;

    int b = bh >> 4, h = bh & 15;
    out[(b*SEQ + s)*(HEADS*DIM) + h*DIM + d] = o;
}

// ---------------- launch ---------------------------------------------------
extern "C" void kernel_launch(void* const* d_in, const int* in_sizes, int n_in,
                              void* d_out, int out_size)
{
    const float* hidden = (const float*)d_in[0];
    const float* Wqk    = (const float*)d_in[1];
    const float* Wv     = (const float*)d_in[2];
    const float* rot    = (const float*)d_in[3];
    float* out = (float*)d_out;

    static int attr_set = 0;
    if (!attr_set) {
        cudaFuncSetAttribute(attn_kernel,
                             cudaFuncAttributeMaxDynamicSharedMemorySize, ATTN_SMEM);
        attr_set = 1;
    }

    proj_kernel<<<dim3(8,64,2), 256>>>(hidden, Wqk, Wv);  // overlapped pipes
    hash_kernel<<<(BH*SEQ)/HTOK, 128>>>(rot);
    sort_kernel<<<BH, 256>>>();
    attn_kernel<<<BH*NCH, 256, ATTN_SMEM>>>();
    combine_kernel<<<(BH*SEQ*DIM)/256, 256>>>(out);
}

// round 14
// speedup vs baseline: 1.6320x; 1.6320x over previous
#include <cuda_runtime.h>
#include <cuda_bf16.h>
#include <math.h>
#include <stdint.h>

// ---------------- problem constants ----------------
#define BATCH 2
#define HEADS 16
#define SEQ   4096
#define DIM   64
#define HID   1024
#define NHASH 2
#define NBUCK 128
#define CHUNK 64
#define BH    (BATCH*HEADS)          // 32
#define SH    (NHASH*SEQ)            // 8192
#define NCH   (SH/CHUNK)             // 128

// ---------------- scratch (device globals; no allocation allowed) ----------
__device__ float g_qk[BH*SEQ*DIM];
__device__ float g_v [BH*SEQ*DIM];
__device__ unsigned char  g_buckets[BH*SH];
__device__ unsigned short g_sorted[BH*SH];
__device__ unsigned short g_undo[BH*SH];
__device__ float g_outs[BH*SH*DIM];
__device__ float g_logits[BH*SH];

// ---------------- SGEMM:  C = A[8192,1024] @ W[1024,1024]^T ---------------
// Double-buffered BK=8, 128x128 tile, 256 threads, 8x8 micro-tile.
// gridDim.z selects (Wqk -> g_qk) or (Wv -> g_v).   (proven R6 config)
__global__ __launch_bounds__(256) void sgemm_kernel(
    const float* __restrict__ A, const float* __restrict__ Wqk,
    const float* __restrict__ Wv)
{
    const int K = HID;
    __shared__ float As[2][8][132];
    __shared__ float Bs[2][8][132];

    const float* W = blockIdx.z ? Wv : Wqk;
    float* Cdst    = blockIdx.z ? g_v : g_qk;

    int bn = blockIdx.x;          // 0..7
    int bm = blockIdx.y;          // 0..63
    int tid = threadIdx.x;
    int tx = tid & 15;
    int ty = tid >> 4;

    int lrow = tid >> 1;
    int kq   = (tid & 1) * 4;
    const float* Aptr = A + ((long)(bm*128 + lrow))*K + kq;
    const float* Wptr = W + ((long)(bn*128 + lrow))*K + kq;

    float acc[8][8];
#pragma unroll
    for (int i = 0; i < 8; i++)
#pragma unroll
        for (int j = 0; j < 8; j++) acc[i][j] = 0.f;

    {
        float4 pa = *(const float4*)(Aptr);
        float4 pb = *(const float4*)(Wptr);
        As[0][kq+0][lrow] = pa.x; As[0][kq+1][lrow] = pa.y;
        As[0][kq+2][lrow] = pa.z; As[0][kq+3][lrow] = pa.w;
        Bs[0][kq+0][lrow] = pb.x; Bs[0][kq+1][lrow] = pb.y;
        Bs[0][kq+2][lrow] = pb.z; Bs[0][kq+3][lrow] = pb.w;
    }
    __syncthreads();

    int stage = 0;
#pragma unroll 1
    for (int k0 = 0; k0 < K; k0 += 8) {
        bool has = (k0 + 8) < K;
        float4 pa, pb;
        if (has) {
            pa = *(const float4*)(Aptr + k0 + 8);
            pb = *(const float4*)(Wptr + k0 + 8);
        }
#pragma unroll
        for (int k = 0; k < 8; k++) {
            float a[8], b[8];
            *(float4*)(a)   = *(const float4*)&As[stage][k][ty*8];
            *(float4*)(a+4) = *(const float4*)&As[stage][k][ty*8+4];
            *(float4*)(b)   = *(const float4*)&Bs[stage][k][tx*4];
            *(float4*)(b+4) = *(const float4*)&Bs[stage][k][64 + tx*4];
#pragma unroll
            for (int i = 0; i < 8; i++)
#pragma unroll
                for (int j = 0; j < 8; j++) acc[i][j] += a[i]*b[j];
        }
        if (has) {
            int ns = stage ^ 1;
            As[ns][kq+0][lrow] = pa.x; As[ns][kq+1][lrow] = pa.y;
            As[ns][kq+2][lrow] = pa.z; As[ns][kq+3][lrow] = pa.w;
            Bs[ns][kq+0][lrow] = pb.x; Bs[ns][kq+1][lrow] = pb.y;
            Bs[ns][kq+2][lrow] = pb.z; Bs[ns][kq+3][lrow] = pb.w;
            __syncthreads();
            stage = ns;
        }
    }

    // vectorized epilogue
#pragma unroll
    for (int i = 0; i < 8; i++) {
        int m = bm*128 + ty*8 + i;
        int b = m >> 12, s = m & 4095;
        int n0 = bn*128 + tx*4;
        int n1 = n0 + 64;
        float4 o0 = make_float4(acc[i][0], acc[i][1], acc[i][2], acc[i][3]);
        float4 o1 = make_float4(acc[i][4], acc[i][5], acc[i][6], acc[i][7]);
        *(float4*)&Cdst[((b*HEADS + (n0>>6))*SEQ + s)*DIM + (n0&63)] = o0;
        *(float4*)&Cdst[((b*HEADS + (n1>>6))*SEQ + s)*DIM + (n1&63)] = o1;
    }
}

// ---------------- hashing: argmax over [rot, -rot] per hash round ----------
#define HTOK 32
__global__ __launch_bounds__(128) void hash_kernel(const float* __restrict__ rot)
{
    __shared__ float rs[DIM*128];       // 32 KB
    __shared__ float q[HTOK][DIM];      // 8 KB
    __shared__ float sv[HTOK][4];
    __shared__ int   si[HTOK][4];

    int tid = threadIdx.x;
    int g0  = blockIdx.x * HTOK;

    for (int i = tid; i < DIM*128; i += 128) rs[i] = rot[i];
    for (int i = tid; i < HTOK*DIM; i += 128) {
        int t = i >> 6, d = i & 63;
        q[t][d] = g_qk[(g0 + t)*DIM + d];
    }
    __syncthreads();

    int warp = tid >> 5, lane = tid & 31;
    int r = tid & 63;

#pragma unroll 4
    for (int t = 0; t < HTOK; t++) {
        float val = 0.f;
#pragma unroll
        for (int d = 0; d < DIM; d++) val += q[t][d] * rs[d*128 + tid];

        float bv; int bi;
        if (val >= -val) { bv = val;  bi = r; }
        else             { bv = -val; bi = r + 64; }
#pragma unroll
        for (int off = 16; off; off >>= 1) {
            float ov = __shfl_down_sync(0xffffffffu, bv, off);
            int   oi = __shfl_down_sync(0xffffffffu, bi, off);
            if (ov > bv || (ov == bv && oi < bi)) { bv = ov; bi = oi; }
        }
        if (lane == 0) { sv[t][warp] = bv; si[t][warp] = bi; }
    }
    __syncthreads();

    if (tid < HTOK*2) {
        int t = tid >> 1, n = tid & 1;
        float v0 = sv[t][n*2];   int i0 = si[t][n*2];
        float v1 = sv[t][n*2+1]; int i1 = si[t][n*2+1];
        if (v1 > v0 || (v1 == v0 && i1 < i0)) { v0 = v1; i0 = i1; }
        int bucket = i0 + n*NBUCK;
        int gidx = g0 + t;
        int bh = gidx >> 12;
        int s  = gidx & 4095;
        g_buckets[bh*SH + n*SEQ + s] = (unsigned char)bucket;
    }
}

// ---------------- stable counting sort per (b,h) ---------------------------
__global__ __launch_bounds__(256) void sort_kernel()
{
    int bh = blockIdx.x;
    __shared__ unsigned char bk[SH];
    __shared__ unsigned int  gh[32][256];
    __shared__ unsigned int  hist[256];
    int tid = threadIdx.x;

    const unsigned char* src = &g_buckets[bh*SH];
    for (int i = tid; i < SH; i += 256) bk[i] = src[i];
    for (int g = 0; g < 32; g++) gh[g][tid] = 0;
    __syncthreads();

    {
        int g = tid >> 3, lane = tid & 7;
        for (int k = 0; k < 32; k++) {
            int idx = g*256 + lane + k*8;
            int pos = idx >> 1, n = idx & 1;
            atomicAdd(&gh[g][bk[n*SEQ + pos]], 1u);
        }
    }
    __syncthreads();

    {
        unsigned int running = 0;
        for (int g = 0; g < 32; g++) {
            unsigned int t = gh[g][tid];
            gh[g][tid] = running;
            running += t;
        }
        hist[tid] = running;
    }
    __syncthreads();
    if (tid == 0) {
        unsigned int acc = 0;
        for (int b = 0; b < 256; b++) { unsigned int t = hist[b]; hist[b] = acc; acc += t; }
    }
    __syncthreads();
    for (int g = 0; g < 32; g++) gh[g][tid] += hist[tid];
    __syncthreads();

    if (tid < 32) {
        unsigned short* outS = &g_sorted[bh*SH];
        unsigned short* outU = &g_undo[bh*SH];
        for (int i = 0; i < 256; i++) {
            int idx = tid*256 + i;
            int pos = idx >> 1, n = idx & 1;
            int t = n*SEQ + pos;
            int b = bk[t];
            unsigned int dest = gh[tid][b]++;
            outS[dest] = (unsigned short)t;
            outU[t]    = (unsigned short)dest;
        }
    }
}

// ---------------- chunked attention ---------------------------------------
// 256 threads. smem: pt ALIASES kt (kt dead after dot accumulation).
// Region sizes: union(kt 64x132, pt 128x68) = 8704 floats; vs = 8704 floats.
// Total ~70.9 KB -> 3 CTAs/SM (was 2 at 104.7 KB).
#define KT_PITCH 132
#define V_PITCH  68
#define P_PITCH  68
#define UNION_FLOATS (128*P_PITCH)     // 8704 >= 64*KT_PITCH (8448)
#define ATTN_SMEM ((UNION_FLOATS + 128*V_PITCH + 128 + 64 + 128)*4)

__global__ __launch_bounds__(256) void attn_kernel()
{
    extern __shared__ float sm[];
    float* kt     = sm;                         // [64 d][132 rows] (phase 1)
    float* pt     = sm;                         // [128 kc][68 q]  (phase 2, alias)
    float* vs     = sm + UNION_FLOATS;          // [128 rows][68 d]
    float* rnorm  = vs + 128*V_PITCH;           // 128
    float* rowlog = rnorm + 128;                // 64
    int*   tick   = (int*)(rowlog + 64);        // 128

    int chunk = blockIdx.x & (NCH-1);
    int bh    = blockIdx.x >> 7;
    int tid   = threadIdx.x;

    if (tid < 128) {
        int sp = (chunk*CHUNK + (SH - CHUNK) + tid) & (SH-1);
        int t  = g_sorted[bh*SH + sp];
        tick[tid] = t & (SEQ-1);
    }
    __syncthreads();

    // cooperative loads: kt transposed (d-major), vs row-major
    for (int rr = 0; rr < 128; rr += 4) {
        int row = rr + (tid >> 6);
        int d   = tid & 63;
        int s   = tick[row];
        int base = (bh*SEQ + s)*DIM + d;
        kt[d*KT_PITCH + row] = g_qk[base];
        vs[row*V_PITCH + d]  = g_v[base];
    }
    __syncthreads();

    if (tid < 128) {
        float ss = 0.f;
#pragma unroll
        for (int d = 0; d < DIM; d++) { float x = kt[d*KT_PITCH + tid]; ss += x*x; }
        rnorm[tid] = rsqrtf(ss * (1.0f/DIM) + 1e-6f) * 0.125f;
    }
    __syncthreads();

    int tx = tid & 15;
    int ty = tid >> 4;

    {
        float acc[8][4];
#pragma unroll
        for (int i = 0; i < 8; i++)
#pragma unroll
            for (int j = 0; j < 4; j++) acc[i][j] = 0.f;

#pragma unroll 4
        for (int d = 0; d < DIM; d++) {
            float a[8], b[4];
            const float* kr = &kt[d*KT_PITCH];
            *(float4*)(a)    = *(const float4*)&kr[ty*8];
            *(float4*)(a+4)  = *(const float4*)&kr[ty*8+4];
            *(float4*)(b)    = *(const float4*)&kr[64 + tx*4];
#pragma unroll
            for (int i = 0; i < 8; i++)
#pragma unroll
                for (int j = 0; j < 4; j++) acc[i][j] += a[i]*b[j];
        }

        int tq[4];
#pragma unroll
        for (int j = 0; j < 4; j++) tq[j] = tick[64 + tx*4 + j];

        // barrier: all kt reads complete before pt (aliased) is written
        __syncthreads();

#pragma unroll
        for (int i = 0; i < 8; i++) {
            int kc = ty*8 + i;
            float rn = rnorm[kc];
            int tk = tick[kc];
            float4 o;
            float v0 = acc[i][0]*rn, v1 = acc[i][1]*rn,
                  v2 = acc[i][2]*rn, v3 = acc[i][3]*rn;
            if (tq[0] <  tk) v0 = -1e9f; else if (tq[0] == tk) v0 = -1e5f;
            if (tq[1] <  tk) v1 = -1e9f; else if (tq[1] == tk) v1 = -1e5f;
            if (tq[2] <  tk) v2 = -1e9f; else if (tq[2] == tk) v2 = -1e5f;
            if (tq[3] <  tk) v3 = -1e9f; else if (tq[3] == tk) v3 = -1e5f;
            o.x = v0; o.y = v1; o.z = v2; o.w = v3;
            *(float4*)&pt[kc*P_PITCH + tx*4] = o;
        }
    }
    __syncthreads();

    {
        int row = tid >> 2, quar = tid & 3;
        float m = -3.4e38f;
        for (int c = 0; c < 32; c++)
            m = fmaxf(m, pt[(quar*32 + c)*P_PITCH + row]);
        m = fmaxf(m, __shfl_xor_sync(0xffffffffu, m, 1));
        m = fmaxf(m, __shfl_xor_sync(0xffffffffu, m, 2));
        float ssum = 0.f;
        for (int c = 0; c < 32; c++)
            ssum += __expf(pt[(quar*32 + c)*P_PITCH + row] - m);
        ssum += __shfl_xor_sync(0xffffffffu, ssum, 1);
        ssum += __shfl_xor_sync(0xffffffffu, ssum, 2);
        float lg = m + __logf(ssum);
        if (quar == 0) rowlog[row] = lg;
        for (int c = 0; c < 32; c++) {
            int idx = (quar*32 + c)*P_PITCH + row;
            pt[idx] = __expf(pt[idx] - lg);
        }
    }
    __syncthreads();

    {
        float acc2[4][4];
#pragma unroll
        for (int i = 0; i < 4; i++)
#pragma unroll
            for (int j = 0; j < 4; j++) acc2[i][j] = 0.f;

#pragma unroll 4
        for (int kc = 0; kc < 128; kc++) {
            float a2[4], b2[4];
            *(float4*)(a2) = *(const float4*)&pt[kc*P_PITCH + ty*4];
            *(float4*)(b2) = *(const float4*)&vs[kc*V_PITCH + tx*4];
#pragma unroll
            for (int i = 0; i < 4; i++)
#pragma unroll
                for (int j = 0; j < 4; j++) acc2[i][j] += a2[i]*b2[j];
        }

#pragma unroll
        for (int i = 0; i < 4; i++) {
            int q = ty*4 + i;
            float4 o; o.x = acc2[i][0]; o.y = acc2[i][1];
                      o.z = acc2[i][2]; o.w = acc2[i][3];
            *(float4*)&g_outs[((long)(bh*SH + chunk*CHUNK + q))*DIM + tx*4] = o;
        }
        if (tid < 64)
            g_logits[bh*SH + chunk*CHUNK + tid] = rowlog[tid];
    }
}

// ---------------- combine hash rounds + write output -----------------------
__global__ __launch_bounds__(256) void combine_kernel(float* __restrict__ out)
{
    int i = blockIdx.x*256 + threadIdx.x;
    int d  = i & 63;
    int r  = i >> 6;
    int s  = r & (SEQ-1);
    int bh = r >> 12;
    int base = bh*SH;

    int p0 = g_undo[base + s];
    int p1 = g_undo[base + SEQ + s];
    float l0 = g_logits[base + p0];
    float l1 = g_logits[base + p1];
    float m  = fmaxf(l0, l1);
    float w0 = __expf(l0 - m);
    float w1 = __expf(l1 - m);
    float inv = 1.0f / (w0 + w1);
    float o = (w0 * g_outs[(base + p0)*DIM + d] +
               w1 * g_outs[(base + p1)*DIM + d]) * inv;

    int b = bh >> 4, h = bh & 15;
    out[(b*SEQ + s)*(HEADS*DIM) + h*DIM + d] = o;
}

// ---------------- launch ---------------------------------------------------
extern "C" void kernel_launch(void* const* d_in, const int* in_sizes, int n_in,
                              void* d_out, int out_size)
{
    const float* hidden = (const float*)d_in[0];
    const float* Wqk    = (const float*)d_in[1];
    const float* Wv     = (const float*)d_in[2];
    const float* rot    = (const float*)d_in[3];
    float* out = (float*)d_out;

    static int attr_set = 0;
    if (!attr_set) {
        cudaFuncSetAttribute(attn_kernel,
                             cudaFuncAttributeMaxDynamicSharedMemorySize, ATTN_SMEM);
        attr_set = 1;
    }

    sgemm_kernel<<<dim3(8,64,2), 256>>>(hidden, Wqk, Wv);
    hash_kernel<<<(BH*SEQ)/HTOK, 128>>>(rot);
    sort_kernel<<<BH, 256>>>();
    attn_kernel<<<BH*NCH, 256, ATTN_SMEM>>>();
    combine_kernel<<<(BH*SEQ*DIM)/256, 256>>>(out);
}

// round 17
// speedup vs baseline: 1.7200x; 1.0539x over previous
#include <cuda_runtime.h>
#include <cuda_bf16.h>
#include <math.h>
#include <stdint.h>

// ---------------- problem constants ----------------
#define BATCH 2
#define HEADS 16
#define SEQ   4096
#define DIM   64
#define HID   1024
#define NHASH 2
#define NBUCK 128
#define CHUNK 64
#define BH    (BATCH*HEADS)          // 32
#define SH    (NHASH*SEQ)            // 8192
#define NCH   (SH/CHUNK)             // 128

// ---------------- scratch (device globals; no allocation allowed) ----------
__device__ float g_qk[BH*SEQ*DIM];
__device__ float g_v [BH*SEQ*DIM];
__device__ unsigned char  g_buckets[BH*SH];
__device__ unsigned short g_sorted[BH*SH];
__device__ unsigned short g_undo[BH*SH];
__device__ float g_outs[BH*SH*DIM];
__device__ float g_logits[BH*SH];

// ---------------- packed f32x2 helpers (Blackwell FFMA2; bit-exact) ---------
typedef unsigned long long u64t;
__device__ __forceinline__ u64t packdup(float x){
    u64t r; asm("mov.b64 %0, {%1, %1};" : "=l"(r) : "f"(x)); return r;
}
__device__ __forceinline__ void ffma2(u64t& d, u64t a, u64t b){
    asm("fma.rn.f32x2 %0, %1, %2, %0;" : "+l"(d) : "l"(a), "l"(b));
}
__device__ __forceinline__ float2 unpack2(u64t v){
    float lo, hi;
    asm("mov.b64 {%0, %1}, %2;" : "=f"(lo), "=f"(hi) : "l"(v));
    return make_float2(lo, hi);
}

// ---------------- SGEMM:  C = A[8192,1024] @ W[1024,1024]^T ---------------
// Double-buffered BK=8, 128x128 tile, 256 threads, 8x8 micro-tile.
// Inner product uses packed fma.rn.f32x2 (two rn fp32 FMAs/instr — results
// bit-identical to the scalar FFMA version). gridDim.z selects qk / v.
__global__ __launch_bounds__(256) void sgemm_kernel(
    const float* __restrict__ A, const float* __restrict__ Wqk,
    const float* __restrict__ Wv)
{
    const int K = HID;
    __shared__ float As[2][8][132];
    __shared__ float Bs[2][8][132];

    const float* W = blockIdx.z ? Wv : Wqk;
    float* Cdst    = blockIdx.z ? g_v : g_qk;

    int bn = blockIdx.x;          // 0..7
    int bm = blockIdx.y;          // 0..63
    int tid = threadIdx.x;
    int tx = tid & 15;
    int ty = tid >> 4;

    int lrow = tid >> 1;
    int kq   = (tid & 1) * 4;
    const float* Aptr = A + ((long)(bm*128 + lrow))*K + kq;
    const float* Wptr = W + ((long)(bn*128 + lrow))*K + kq;

    // packed accumulators: acc2[i][j] = (C[i][2j], C[i][2j+1]) pairs
    u64t acc2[8][4];
#pragma unroll
    for (int i = 0; i < 8; i++)
#pragma unroll
        for (int j = 0; j < 4; j++) acc2[i][j] = 0ULL;   // (+0.0f, +0.0f)

    {
        float4 pa = *(const float4*)(Aptr);
        float4 pb = *(const float4*)(Wptr);
        As[0][kq+0][lrow] = pa.x; As[0][kq+1][lrow] = pa.y;
        As[0][kq+2][lrow] = pa.z; As[0][kq+3][lrow] = pa.w;
        Bs[0][kq+0][lrow] = pb.x; Bs[0][kq+1][lrow] = pb.y;
        Bs[0][kq+2][lrow] = pb.z; Bs[0][kq+3][lrow] = pb.w;
    }
    __syncthreads();

    int stage = 0;
#pragma unroll 1
    for (int k0 = 0; k0 < K; k0 += 8) {
        bool has = (k0 + 8) < K;
        float4 pa, pb;
        if (has) {
            pa = *(const float4*)(Aptr + k0 + 8);
            pb = *(const float4*)(Wptr + k0 + 8);
        }
#pragma unroll
        for (int k = 0; k < 8; k++) {
            float a[8];
            u64t b2[4];
            *(float4*)(a)   = *(const float4*)&As[stage][k][ty*8];
            *(float4*)(a+4) = *(const float4*)&As[stage][k][ty*8+4];
            // b pairs arrive pre-packed from smem (16B-aligned)
            *(ulonglong2*)(b2)   = *(const ulonglong2*)&Bs[stage][k][tx*4];
            *(ulonglong2*)(b2+2) = *(const ulonglong2*)&Bs[stage][k][64 + tx*4];
#pragma unroll
            for (int i = 0; i < 8; i++) {
                u64t ad = packdup(a[i]);
#pragma unroll
                for (int j = 0; j < 4; j++) ffma2(acc2[i][j], ad, b2[j]);
            }
        }
        if (has) {
            int ns = stage ^ 1;
            As[ns][kq+0][lrow] = pa.x; As[ns][kq+1][lrow] = pa.y;
            As[ns][kq+2][lrow] = pa.z; As[ns][kq+3][lrow] = pa.w;
            Bs[ns][kq+0][lrow] = pb.x; Bs[ns][kq+1][lrow] = pb.y;
            Bs[ns][kq+2][lrow] = pb.z; Bs[ns][kq+3][lrow] = pb.w;
            __syncthreads();
            stage = ns;
        }
    }

    // vectorized epilogue (unpack pairs; same layout as before)
#pragma unroll
    for (int i = 0; i < 8; i++) {
        int m = bm*128 + ty*8 + i;
        int b = m >> 12, s = m & 4095;
        int n0 = bn*128 + tx*4;
        int n1 = n0 + 64;
        float2 p0 = unpack2(acc2[i][0]);
        float2 p1 = unpack2(acc2[i][1]);
        float2 p2 = unpack2(acc2[i][2]);
        float2 p3 = unpack2(acc2[i][3]);
        float4 o0 = make_float4(p0.x, p0.y, p1.x, p1.y);
        float4 o1 = make_float4(p2.x, p2.y, p3.x, p3.y);
        *(float4*)&Cdst[((b*HEADS + (n0>>6))*SEQ + s)*DIM + (n0&63)] = o0;
        *(float4*)&Cdst[((b*HEADS + (n1>>6))*SEQ + s)*DIM + (n1&63)] = o1;
    }
}

// ---------------- hashing: argmax over [rot, -rot] per hash round ----------
#define HTOK 32
__global__ __launch_bounds__(128) void hash_kernel(const float* __restrict__ rot)
{
    __shared__ float rs[DIM*128];       // 32 KB
    __shared__ float q[HTOK][DIM];      // 8 KB
    __shared__ float sv[HTOK][4];
    __shared__ int   si[HTOK][4];

    int tid = threadIdx.x;
    int g0  = blockIdx.x * HTOK;

    for (int i = tid; i < DIM*128; i += 128) rs[i] = rot[i];
    for (int i = tid; i < HTOK*DIM; i += 128) {
        int t = i >> 6, d = i & 63;
        q[t][d] = g_qk[(g0 + t)*DIM + d];
    }
    __syncthreads();

    int warp = tid >> 5, lane = tid & 31;
    int r = tid & 63;

#pragma unroll 4
    for (int t = 0; t < HTOK; t++) {
        float val = 0.f;
#pragma unroll
        for (int d = 0; d < DIM; d++) val += q[t][d] * rs[d*128 + tid];

        float bv; int bi;
        if (val >= -val) { bv = val;  bi = r; }
        else             { bv = -val; bi = r + 64; }
#pragma unroll
        for (int off = 16; off; off >>= 1) {
            float ov = __shfl_down_sync(0xffffffffu, bv, off);
            int   oi = __shfl_down_sync(0xffffffffu, bi, off);
            if (ov > bv || (ov == bv && oi < bi)) { bv = ov; bi = oi; }
        }
        if (lane == 0) { sv[t][warp] = bv; si[t][warp] = bi; }
    }
    __syncthreads();

    if (tid < HTOK*2) {
        int t = tid >> 1, n = tid & 1;
        float v0 = sv[t][n*2];   int i0 = si[t][n*2];
        float v1 = sv[t][n*2+1]; int i1 = si[t][n*2+1];
        if (v1 > v0 || (v1 == v0 && i1 < i0)) { v0 = v1; i0 = i1; }
        int bucket = i0 + n*NBUCK;
        int gidx = g0 + t;
        int bh = gidx >> 12;
        int s  = gidx & 4095;
        g_buckets[bh*SH + n*SEQ + s] = (unsigned char)bucket;
    }
}

// ---------------- stable counting sort per (b,h) ---------------------------
__global__ __launch_bounds__(256) void sort_kernel()
{
    int bh = blockIdx.x;
    __shared__ unsigned char bk[SH];
    __shared__ unsigned int  gh[32][256];
    __shared__ unsigned int  hist[256];
    int tid = threadIdx.x;

    const unsigned char* src = &g_buckets[bh*SH];
    for (int i = tid; i < SH; i += 256) bk[i] = src[i];
    for (int g = 0; g < 32; g++) gh[g][tid] = 0;
    __syncthreads();

    {
        int g = tid >> 3, lane = tid & 7;
        for (int k = 0; k < 32; k++) {
            int idx = g*256 + lane + k*8;
            int pos = idx >> 1, n = idx & 1;
            atomicAdd(&gh[g][bk[n*SEQ + pos]], 1u);
        }
    }
    __syncthreads();

    {
        unsigned int running = 0;
        for (int g = 0; g < 32; g++) {
            unsigned int t = gh[g][tid];
            gh[g][tid] = running;
            running += t;
        }
        hist[tid] = running;
    }
    __syncthreads();
    if (tid == 0) {
        unsigned int acc = 0;
        for (int b = 0; b < 256; b++) { unsigned int t = hist[b]; hist[b] = acc; acc += t; }
    }
    __syncthreads();
    for (int g = 0; g < 32; g++) gh[g][tid] += hist[tid];
    __syncthreads();

    if (tid < 32) {
        unsigned short* outS = &g_sorted[bh*SH];
        unsigned short* outU = &g_undo[bh*SH];
        for (int i = 0; i < 256; i++) {
            int idx = tid*256 + i;
            int pos = idx >> 1, n = idx & 1;
            int t = n*SEQ + pos;
            int b = bk[t];
            unsigned int dest = gh[tid][b]++;
            outS[dest] = (unsigned short)t;
            outU[t]    = (unsigned short)dest;
        }
    }
}

// ---------------- chunked attention (R14 winner, unchanged) -----------------
#define KT_PITCH 132
#define V_PITCH  68
#define P_PITCH  68
#define UNION_FLOATS (128*P_PITCH)     // 8704 >= 64*KT_PITCH (8448)
#define ATTN_SMEM ((UNION_FLOATS + 128*V_PITCH + 128 + 64 + 128)*4)

__global__ __launch_bounds__(256) void attn_kernel()
{
    extern __shared__ float sm[];
    float* kt     = sm;                         // [64 d][132 rows] (phase 1)
    float* pt     = sm;                         // [128 kc][68 q]  (phase 2, alias)
    float* vs     = sm + UNION_FLOATS;          // [128 rows][68 d]
    float* rnorm  = vs + 128*V_PITCH;           // 128
    float* rowlog = rnorm + 128;                // 64
    int*   tick   = (int*)(rowlog + 64);        // 128

    int chunk = blockIdx.x & (NCH-1);
    int bh    = blockIdx.x >> 7;
    int tid   = threadIdx.x;

    if (tid < 128) {
        int sp = (chunk*CHUNK + (SH - CHUNK) + tid) & (SH-1);
        int t  = g_sorted[bh*SH + sp];
        tick[tid] = t & (SEQ-1);
    }
    __syncthreads();

    for (int rr = 0; rr < 128; rr += 4) {
        int row = rr + (tid >> 6);
        int d   = tid & 63;
        int s   = tick[row];
        int base = (bh*SEQ + s)*DIM + d;
        kt[d*KT_PITCH + row] = g_qk[base];
        vs[row*V_PITCH + d]  = g_v[base];
    }
    __syncthreads();

    if (tid < 128) {
        float ss = 0.f;
#pragma unroll
        for (int d = 0; d < DIM; d++) { float x = kt[d*KT_PITCH + tid]; ss += x*x; }
        rnorm[tid] = rsqrtf(ss * (1.0f/DIM) + 1e-6f) * 0.125f;
    }
    __syncthreads();

    int tx = tid & 15;
    int ty = tid >> 4;

    {
        float acc[8][4];
#pragma unroll
        for (int i = 0; i < 8; i++)
#pragma unroll
            for (int j = 0; j < 4; j++) acc[i][j] = 0.f;

#pragma unroll 4
        for (int d = 0; d < DIM; d++) {
            float a[8], b[4];
            const float* kr = &kt[d*KT_PITCH];
            *(float4*)(a)    = *(const float4*)&kr[ty*8];
            *(float4*)(a+4)  = *(const float4*)&kr[ty*8+4];
            *(float4*)(b)    = *(const float4*)&kr[64 + tx*4];
#pragma unroll
            for (int i = 0; i < 8; i++)
#pragma unroll
                for (int j = 0; j < 4; j++) acc[i][j] += a[i]*b[j];
        }

        int tq[4];
#pragma unroll
        for (int j = 0; j < 4; j++) tq[j] = tick[64 + tx*4 + j];

        // barrier: all kt reads complete before pt (aliased) is written
        __syncthreads();

#pragma unroll
        for (int i = 0; i < 8; i++) {
            int kc = ty*8 + i;
            float rn = rnorm[kc];
            int tk = tick[kc];
            float4 o;
            float v0 = acc[i][0]*rn, v1 = acc[i][1]*rn,
                  v2 = acc[i][2]*rn, v3 = acc[i][3]*rn;
            if (tq[0] <  tk) v0 = -1e9f; else if (tq[0] == tk) v0 = -1e5f;
            if (tq[1] <  tk) v1 = -1e9f; else if (tq[1] == tk) v1 = -1e5f;
            if (tq[2] <  tk) v2 = -1e9f; else if (tq[2] == tk) v2 = -1e5f;
            if (tq[3] <  tk) v3 = -1e9f; else if (tq[3] == tk) v3 = -1e5f;
            o.x = v0; o.y = v1; o.z = v2; o.w = v3;
            *(float4*)&pt[kc*P_PITCH + tx*4] = o;
        }
    }
    __syncthreads();

    {
        int row = tid >> 2, quar = tid & 3;
        float m = -3.4e38f;
        for (int c = 0; c < 32; c++)
            m = fmaxf(m, pt[(quar*32 + c)*P_PITCH + row]);
        m = fmaxf(m, __shfl_xor_sync(0xffffffffu, m, 1));
        m = fmaxf(m, __shfl_xor_sync(0xffffffffu, m, 2));
        float ssum = 0.f;
        for (int c = 0; c < 32; c++)
            ssum += __expf(pt[(quar*32 + c)*P_PITCH + row] - m);
        ssum += __shfl_xor_sync(0xffffffffu, ssum, 1);
        ssum += __shfl_xor_sync(0xffffffffu, ssum, 2);
        float lg = m + __logf(ssum);
        if (quar == 0) rowlog[row] = lg;
        for (int c = 0; c < 32; c++) {
            int idx = (quar*32 + c)*P_PITCH + row;
            pt[idx] = __expf(pt[idx] - lg);
        }
    }
    __syncthreads();

    {
        float acc2[4][4];
#pragma unroll
        for (int i = 0; i < 4; i++)
#pragma unroll
            for (int j = 0; j < 4; j++) acc2[i][j] = 0.f;

#pragma unroll 4
        for (int kc = 0; kc < 128; kc++) {
            float a2[4], b2[4];
            *(float4*)(a2) = *(const float4*)&pt[kc*P_PITCH + ty*4];
            *(float4*)(b2) = *(const float4*)&vs[kc*V_PITCH + tx*4];
#pragma unroll
            for (int i = 0; i < 4; i++)
#pragma unroll
                for (int j = 0; j < 4; j++) acc2[i][j] += a2[i]*b2[j];
        }

#pragma unroll
        for (int i = 0; i < 4; i++) {
            int q = ty*4 + i;
            float4 o; o.x = acc2[i][0]; o.y = acc2[i][1];
                      o.z = acc2[i][2]; o.w = acc2[i][3];
            *(float4*)&g_outs[((long)(bh*SH + chunk*CHUNK + q))*DIM + tx*4] = o;
        }
        if (tid < 64)
            g_logits[bh*SH + chunk*CHUNK + tid] = rowlog[tid];
    }
}

// ---------------- combine hash rounds + write output -----------------------
__global__ __launch_bounds__(256) void combine_kernel(float* __restrict__ out)
{
    int i = blockIdx.x*256 + threadIdx.x;
    int d  = i & 63;
    int r  = i >> 6;
    int s  = r & (SEQ-1);
    int bh = r >> 12;
    int base = bh*SH;

    int p0 = g_undo[base + s];
    int p1 = g_undo[base + SEQ + s];
    float l0 = g_logits[base + p0];
    float l1 = g_logits[base + p1];
    float m  = fmaxf(l0, l1);
    float w0 = __expf(l0 - m);
    float w1 = __expf(l1 - m);
    float inv = 1.0f / (w0 + w1);
    float o = (w0 * g_outs[(base + p0)*DIM + d] +
               w1 * g_outs[(base + p1)*DIM + d]) * inv;

    int b = bh >> 4, h = bh & 15;
    out[(b*SEQ + s)*(HEADS*DIM) + h*DIM + d] = o;
}

// ---------------- launch ---------------------------------------------------
extern "C" void kernel_launch(void* const* d_in, const int* in_sizes, int n_in,
                              void* d_out, int out_size)
{
    const float* hidden = (const float*)d_in[0];
    const float* Wqk    = (const float*)d_in[1];
    const float* Wv     = (const float*)d_in[2];
    const float* rot    = (const float*)d_in[3];
    float* out = (float*)d_out;

    static int attr_set = 0;
    if (!attr_set) {
        cudaFuncSetAttribute(attn_kernel,
                             cudaFuncAttributeMaxDynamicSharedMemorySize, ATTN_SMEM);
        attr_set = 1;
    }

    sgemm_kernel<<<dim3(8,64,2), 256>>>(hidden, Wqk, Wv);
    hash_kernel<<<(BH*SEQ)/HTOK, 128>>>(rot);
    sort_kernel<<<BH, 256>>>();
    attn_kernel<<<BH*NCH, 256, ATTN_SMEM>>>();
    combine_kernel<<<(BH*SEQ*DIM)/256, 256>>>(out);
}